// round 7
// baseline (speedup 1.0000x reference)
#include <cuda_runtime.h>
#include <math.h>

// z = (1, cos x0, sin x0) . M . (1, cos x1, sin x1)^T per element, then sigmoid.
// M (3x3) derives from S = Re(U^dag (Z x I) U) of the pair-0 2-qubit circuit.
// EPT=4: each thread front-batches 4 independent LDG.64s (maximizes bytes in
// flight — the kernel is DRAM-latency/concurrency bound, traffic is fixed at
// ~4.5MB by sector granularity). Warp 0 computes M lane-parallel under the
// load shadow; per-element trig is hoisted above the barrier.

__global__ void __launch_bounds__(128, 8) qcnn_kernel(
    const float* __restrict__ inputs,   // (B, 8) row-major
    const float* __restrict__ params,   // (48,)
    float* __restrict__ out,            // (B,)
    int n)
{
    const unsigned FULL = 0xffffffffu;
    __shared__ float sM[9];

    int t = blockIdx.x * blockDim.x + threadIdx.x;
    int base = t * 4;

    // ---- Front-batch 4 independent input loads (32 sectors in flight/thread) ----
    const float2* in2 = reinterpret_cast<const float2*>(inputs);
    float2 x0 = make_float2(0.f, 0.f), x1 = x0, x2 = x0, x3 = x0;
    bool valid = (base + 3) < n;
    if (valid) {
        x0 = __ldg(in2 + (base + 0) * 4);
        x1 = __ldg(in2 + (base + 1) * 4);
        x2 = __ldg(in2 + (base + 2) * 4);
        x3 = __ldg(in2 + (base + 3) * 4);
    }

    // ---- Warp 0: lane-parallel prologue (lane = r*4+c holds U[r][c]) ----
    if (threadIdx.x < 32) {
        int lane = threadIdx.x;
        int r = (lane >> 2) & 3;
        int c = lane & 3;
        bool rb0 = (r & 1) != 0;
        bool rb1 = ((r >> 1) & 1) != 0;

        float sh[12], ch[12];
#pragma unroll
        for (int layer = 0; layer < 3; layer++) {
#pragma unroll
            for (int q = 0; q < 4; q++) {
                float p = __ldg(params + layer * 16 + q);
                __sincosf(0.5f * p, &sh[layer * 4 + q], &ch[layer * 4 + q]);
            }
        }

        float ux = (r == c) ? 1.0f : 0.0f;
        float uy = 0.0f;

#pragma unroll
        for (int layer = 0; layer < 3; layer++) {
            float c0 = ch[layer * 4 + 0], s0 = sh[layer * 4 + 0];
            float c1 = ch[layer * 4 + 1], s1 = sh[layer * 4 + 1];
            float c2 = ch[layer * 4 + 2], s2 = sh[layer * 4 + 2];
            float c3 = ch[layer * 4 + 3], s3 = sh[layer * 4 + 3];

            { // RZ on qubit A
                float py = rb1 ? s0 : -s0;
                float nx = c0 * ux - py * uy;
                float ny = fmaf(c0, uy, py * ux);
                ux = nx; uy = ny;
            }
            { // RX on qubit B (partner row lane^4)
                float px = __shfl_xor_sync(FULL, ux, 4);
                float py = __shfl_xor_sync(FULL, uy, 4);
                float nx = fmaf(c1, ux,  s1 * py);
                float ny = fmaf(c1, uy, -s1 * px);
                ux = nx; uy = ny;
            }
            { // CNOT(A->B): rows 2<->3
                float px = __shfl_xor_sync(FULL, ux, 4);
                float py = __shfl_xor_sync(FULL, uy, 4);
                if (rb1) { ux = px; uy = py; }
            }
            { // RZ on qubit B
                float py = rb0 ? s2 : -s2;
                float nx = c2 * ux - py * uy;
                float ny = fmaf(c2, uy, py * ux);
                ux = nx; uy = ny;
            }
            { // RX on qubit B
                float px = __shfl_xor_sync(FULL, ux, 4);
                float py = __shfl_xor_sync(FULL, uy, 4);
                float nx = fmaf(c3, ux,  s3 * py);
                float ny = fmaf(c3, uy, -s3 * px);
                ux = nx; uy = ny;
            }
        }

        // S[k][l] = sum_m z_m Re(conj(U[m][k]) U[m][l]), z=(+1,+1,-1,-1)
        float Sval = 0.0f;
#pragma unroll
        for (int m = 0; m < 4; m++) {
            float ax = __shfl_sync(FULL, ux, m * 4 + r);
            float ay = __shfl_sync(FULL, uy, m * 4 + r);
            float bx = __shfl_sync(FULL, ux, m * 4 + c);
            float by = __shfl_sync(FULL, uy, m * 4 + c);
            float term = fmaf(ax, bx, ay * by);
            Sval += (m < 2) ? term : -term;
        }

        // Fold half-angle quadratic form -> full-angle bilinear form.
        const int   Atab[3][2] = { {0,1}, {0,1}, {0,1} };
        const int   Ctab[3][2] = { {0,1}, {0,1}, {1,0} };
        const float Wtab[3][2] = { {0.5f,0.5f}, {0.5f,-0.5f}, {0.5f,0.5f} };

        int mu = lane / 3, mv = lane - mu * 3;
        if (lane >= 9) { mu = 0; mv = 0; }

        float Macc = 0.0f;
#pragma unroll
        for (int i = 0; i < 2; i++) {
#pragma unroll
            for (int j = 0; j < 2; j++) {
                int k   = 2 * Atab[mu][i] + Atab[mv][j];
                int l   = 2 * Ctab[mu][i] + Ctab[mv][j];
                float w = Wtab[mu][i] * Wtab[mv][j];
                float s = __shfl_sync(FULL, Sval, k * 4 + l);
                Macc = fmaf(w, s, Macc);
            }
        }
        if (lane < 9) sM[lane] = Macc;
    }

    // ---- Per-element trig (independent of M; overlaps prologue/barrier) ----
    float Ca[4], Sa[4], Cb[4], Sb[4];
    __sincosf(x0.x, &Sa[0], &Ca[0]); __sincosf(x0.y, &Sb[0], &Cb[0]);
    __sincosf(x1.x, &Sa[1], &Ca[1]); __sincosf(x1.y, &Sb[1], &Cb[1]);
    __sincosf(x2.x, &Sa[2], &Ca[2]); __sincosf(x2.y, &Sb[2], &Cb[2]);
    __sincosf(x3.x, &Sa[3], &Ca[3]); __sincosf(x3.y, &Sb[3], &Cb[3]);

    __syncthreads();

    if (!valid) return;

    float m0 = sM[0], m1 = sM[1], m2 = sM[2];
    float m3 = sM[3], m4 = sM[4], m5 = sM[5];
    float m6 = sM[6], m7 = sM[7], m8 = sM[8];

    float res[4];
#pragma unroll
    for (int i = 0; i < 4; i++) {
        float a0 = fmaf(m2, Sb[i], fmaf(m1, Cb[i], m0));
        float a1 = fmaf(m5, Sb[i], fmaf(m4, Cb[i], m3));
        float a2 = fmaf(m8, Sb[i], fmaf(m7, Cb[i], m6));
        float z  = fmaf(a2, Sa[i], fmaf(a1, Ca[i], a0));
        res[i] = __fdividef(1.0f, 1.0f + __expf(-z));
    }

    reinterpret_cast<float4*>(out)[t] = make_float4(res[0], res[1], res[2], res[3]);
}

extern "C" void kernel_launch(void* const* d_in, const int* in_sizes, int n_in,
                              void* d_out, int out_size) {
    const float* inputs = (const float*)d_in[0];
    const float* params = (const float*)d_in[1];
    float* out = (float*)d_out;

    int n = out_size;  // 131072
    int threads = 128;
    int elems_per_block = threads * 4;                       // 512
    int blocks = (n + elems_per_block - 1) / elems_per_block; // 256
    qcnn_kernel<<<blocks, threads>>>(inputs, params, out, n);
}

// round 8
// speedup vs baseline: 1.0335x; 1.0335x over previous
#include <cuda_runtime.h>
#include <math.h>

// Exact collapse of the reference circuit:
// The observable is Z on qubit 0. The only gates touching qubit 0 after the
// initial RY(x0) are RZ (diagonal) and CNOT *controls* (diagonal on the
// control) — all commute with Z_0, so U^dag Z_0 U = Z_0 and
//   z = <psi_init| Z_0 |psi_init> = cos(x0),
// independent of params and of x1..x7. Output = sigmoid(cos(x[:,0])).
//
// Memory traffic is fixed at ~4.5MB by 32B-sector granularity (each 32B input
// row contributes the one float we need). Kernel is a pure streaming map.

__global__ void __launch_bounds__(256) qcnn_kernel(
    const float* __restrict__ inputs,   // (B, 8) row-major; only column 0 used
    float* __restrict__ out,            // (B,)
    int n)
{
    int t = blockIdx.x * blockDim.x + threadIdx.x;
    if (t >= n) return;

    float x0 = __ldg(inputs + t * 8);
    float z  = __cosf(x0);
    out[t] = __fdividef(1.0f, 1.0f + __expf(-z));
}

extern "C" void kernel_launch(void* const* d_in, const int* in_sizes, int n_in,
                              void* d_out, int out_size) {
    const float* inputs = (const float*)d_in[0];
    float* out = (float*)d_out;

    int n = out_size;  // 131072
    int threads = 256;
    int blocks = (n + threads - 1) / threads;  // 512
    qcnn_kernel<<<blocks, threads>>>(inputs, out, n);
}